// round 12
// baseline (speedup 1.0000x reference)
#include <cuda_runtime.h>
#include <cuda_bf16.h>

// Gather3d: x [1, 128, 16, 128, 128] f32, active_indices [128, 2] i32 in [0,112)
// out [128, 128, 18, 16, 16] f32:
//   out[n, c, T, i, j] = (T < 2) ? 0 : x[0, c, T-2, idx_y[n]+i, idx_x[n]+j]
//
// R9: L1tex-wavefront-optimized mapping.
//   - CTA = one (n, c) pair; 256 threads = the 16x16 (i, j) spatial block.
//     A warp's LDG.32 spans only 2 input rows (vs 8 before) -> ~2-3 L1
//     wavefronts per 128 B loaded instead of ~8. Warp stores are 128 B
//     contiguous, 128 B aligned -> 1 wavefront.
//   - Each thread loops T = 2..17 with constant strides, amortizing all index
//     math; full unroll gives MLP ~16 independent loads.
//   - Grid order: c outer, n inner -> all 128 n-CTAs reading a (c,T) plane are
//     resident together; each 64 KB plane is DRAM-fetched once, L2-reused.
//   - __stcs streaming stores keep the 302 MB write stream out of L2.

#define CC   128   // channels
#define TIN  16    // input time
#define TT   18    // output time (TIN + 2 zero pad frames)
#define HW   128   // H == W
#define NN   128   // number of active blocks
#define BH   16
#define BW   16

__global__ __launch_bounds__(256) void gather3d_kernel(
    const float* __restrict__ x,
    const int*   __restrict__ idx,
    float*       __restrict__ out)
{
    // blockIdx.x = c * NN + n  (n inner for cross-n L2 reuse of (c,T) planes)
    int n = blockIdx.x & (NN - 1);
    int c = blockIdx.x >> 7;

    int j = threadIdx.x & (BW - 1);   // col within block
    int i = threadIdx.x >> 4;         // row within block

    int iy = __ldg(&idx[2 * n]);      // broadcast across CTA
    int ix = __ldg(&idx[2 * n + 1]);

    // input pointer for T=2 (input t=0); stride per T = one plane = 128*128
    const float* src = x + ((c * TIN + 0) * HW + (iy + i)) * HW + (ix + j);
    // output pointer for this (n, c); chunk is TT*256 floats, 1 KB-aligned rows
    float* dst = out + ((n * CC + c) * TT) * (BH * BW) + i * BW + j;

    // T = 0, 1: zero pad frames (d_out is poisoned, must write zeros)
    __stcs(dst, 0.0f);
    __stcs(dst + BH * BW, 0.0f);
    dst += 2 * BH * BW;

#pragma unroll
    for (int t = 0; t < TIN; ++t) {
        float v = __ldg(src + t * (HW * HW));
        __stcs(dst + t * (BH * BW), v);
    }
}

extern "C" void kernel_launch(void* const* d_in, const int* in_sizes, int n_in,
                              void* d_out, int out_size) {
    const float* x   = (const float*)d_in[0];
    const int*   idx = (const int*)d_in[1];
    float*       out = (float*)d_out;

    gather3d_kernel<<<CC * NN, 256>>>(x, idx, out);  // 16384 CTAs
}